// round 7
// baseline (speedup 1.0000x reference)
#include <cuda_runtime.h>
#include <cuda_bf16.h>
#include <math.h>
#include <stdint.h>

#define Gg 8
#define Ee 8
#define Ss 1024
#define Cc 256
#define Mdim 1024
#define Hh 5464
#define Hp 5504
#define Ntok (Gg*Ss)
#define GCv (Gg*Cc)

// ---------------- device scratch ----------------
__device__ __align__(256) __nv_bfloat16 g_a_hi [(size_t)Ee*GCv*Mdim];
__device__ __align__(256) __nv_bfloat16 g_a_lo [(size_t)Ee*GCv*Mdim];
__device__ __align__(256) __nv_bfloat16 g_w0t_hi[(size_t)Ee*Hp*Mdim];
__device__ __align__(256) __nv_bfloat16 g_w0t_lo[(size_t)Ee*Hp*Mdim];
__device__ __align__(256) __nv_bfloat16 g_w1t_hi[(size_t)Ee*Hp*Mdim];
__device__ __align__(256) __nv_bfloat16 g_w1t_lo[(size_t)Ee*Hp*Mdim];
__device__ __align__(256) __nv_bfloat16 g_wot_hi[(size_t)Ee*Mdim*Hp];
__device__ __align__(256) __nv_bfloat16 g_wot_lo[(size_t)Ee*Mdim*Hp];
__device__ __align__(256) __nv_bfloat16 g_hid_hi[(size_t)Ee*GCv*Hp];
__device__ __align__(256) __nv_bfloat16 g_hid_lo[(size_t)Ee*GCv*Hp];
__device__ __align__(256) float g_expout[(size_t)Ee*GCv*Mdim];
__device__ int   g_idx1[Ntok];
__device__ int   g_idx2[Ntok];
__device__ float g_gate1[Ntok];
__device__ float g_gate2[Ntok];
__device__ int   g_slotsrc[Ee*GCv];
__device__ int2  g_tokinfo[Ntok];

// ---------------- helpers ----------------
__device__ __forceinline__ uint32_t s2u(const void* p){
    uint32_t a; asm("{ .reg .u64 t; cvta.to.shared.u64 t, %1; cvt.u32.u64 %0, t; }":"=r"(a):"l"(p)); return a;
}
__device__ __forceinline__ void cpa16(uint32_t d, const void* s){
    asm volatile("cp.async.cg.shared.global [%0], [%1], 16;"::"r"(d),"l"(s));
}
#define CP_COMMIT() asm volatile("cp.async.commit_group;":::"memory")
#define CP_WAIT2()  asm volatile("cp.async.wait_group 2;":::"memory")
#define CP_WAIT1()  asm volatile("cp.async.wait_group 1;":::"memory")
#define CP_WAIT0()  asm volatile("cp.async.wait_group 0;":::"memory")

#define LDSM4(R, addr) \
    asm volatile("ldmatrix.sync.aligned.m8n8.x4.shared.b16 {%0,%1,%2,%3}, [%4];" \
        : "=r"((R)[0]),"=r"((R)[1]),"=r"((R)[2]),"=r"((R)[3]) : "r"(addr))
#define LDSM2(R, addr) \
    asm volatile("ldmatrix.sync.aligned.m8n8.x2.shared.b16 {%0,%1}, [%2];" \
        : "=r"((R)[0]),"=r"((R)[1]) : "r"(addr))
#define MMA_BF16(D, A, B) \
    asm volatile("mma.sync.aligned.m16n8k16.row.col.f32.bf16.bf16.f32 " \
        "{%0,%1,%2,%3}, {%4,%5,%6,%7}, {%8,%9}, {%0,%1,%2,%3};" \
        : "+f"((D)[0]),"+f"((D)[1]),"+f"((D)[2]),"+f"((D)[3]) \
        : "r"((A)[0]),"r"((A)[1]),"r"((A)[2]),"r"((A)[3]), "r"((B)[0]),"r"((B)[1]))

__device__ __forceinline__ void split1(float a, __nv_bfloat16& h, __nv_bfloat16& l){
    h = __float2bfloat16(a); l = __float2bfloat16(a - __bfloat162float(h));
}
__device__ __forceinline__ uint32_t packbf(__nv_bfloat16 a, __nv_bfloat16 b){
    return (uint32_t)__bfloat16_as_ushort(a) | ((uint32_t)__bfloat16_as_ushort(b) << 16);
}
__device__ __forceinline__ float gelu_f(float x){
    float u = 0.7978845608028654f*(x + 0.044715f*x*x*x);
    return 0.5f*x*(1.f + tanhf(u));
}

// ---------- router ----------
__global__ void k_router(const float* __restrict__ x, const float* __restrict__ rw){
    int t = (blockIdx.x*blockDim.x + threadIdx.x) >> 5;
    int lane = threadIdx.x & 31;
    if (t >= Ntok) return;
    const float* xr = x + (size_t)t*Mdim;
    float acc[Ee];
#pragma unroll
    for (int e = 0; e < Ee; e++) acc[e] = 0.f;
    for (int m = lane; m < Mdim; m += 32){
        float xv = xr[m];
        const float4* r4 = (const float4*)(rw + m*Ee);
        float4 rA = r4[0], rB = r4[1];
        acc[0]=fmaf(xv,rA.x,acc[0]); acc[1]=fmaf(xv,rA.y,acc[1]);
        acc[2]=fmaf(xv,rA.z,acc[2]); acc[3]=fmaf(xv,rA.w,acc[3]);
        acc[4]=fmaf(xv,rB.x,acc[4]); acc[5]=fmaf(xv,rB.y,acc[5]);
        acc[6]=fmaf(xv,rB.z,acc[6]); acc[7]=fmaf(xv,rB.w,acc[7]);
    }
#pragma unroll
    for (int e = 0; e < Ee; e++)
#pragma unroll
        for (int o = 16; o > 0; o >>= 1)
            acc[e] += __shfl_xor_sync(0xffffffffu, acc[e], o);
    if (lane == 0){
        float mx = acc[0];
#pragma unroll
        for (int e = 1; e < Ee; e++) mx = fmaxf(mx, acc[e]);
        float p[Ee]; float sum = 0.f;
#pragma unroll
        for (int e = 0; e < Ee; e++){ p[e] = expf(acc[e]-mx); sum += p[e]; }
        float inv = 1.f/sum;
#pragma unroll
        for (int e = 0; e < Ee; e++) p[e] *= inv;
        int i1 = 0; float b1 = p[0];
#pragma unroll
        for (int e = 1; e < Ee; e++) if (p[e] > b1){ b1 = p[e]; i1 = e; }
        int i2 = -1; float b2 = -1.f;
#pragma unroll
        for (int e = 0; e < Ee; e++) if (e != i1 && p[e] > b2){ b2 = p[e]; i2 = e; }
        g_idx1[t]=i1; g_idx2[t]=i2; g_gate1[t]=b1; g_gate2[t]=b2;
    }
}

// ---------- capacity ----------
__global__ void k_capacity(){
    int g = blockIdx.x, tid = threadIdx.x;
    __shared__ int s_i1[Ss], s_i2[Ss], s_p1[Ss], s_p2[Ss];
    __shared__ int s_slot[Ee*Cc];
    __shared__ int s_cnt[Ee], s_m1c[Ee];
    for (int s = tid; s < Ss; s += blockDim.x){
        s_i1[s] = g_idx1[g*Ss+s]; s_i2[s] = g_idx2[g*Ss+s];
    }
    for (int i = tid; i < Ee*Cc; i += blockDim.x) s_slot[i] = -1;
    if (tid < Ee) s_cnt[tid] = 0;
    __syncthreads();
    if (tid == 0){
        for (int s = 0; s < Ss; s++){
            int e = s_i1[s]; int p = s_cnt[e]++;
            if (p < Cc){ s_p1[s] = p; s_slot[e*Cc+p] = s; } else s_p1[s] = -1;
        }
#pragma unroll
        for (int e = 0; e < Ee; e++){ s_m1c[e] = min(s_cnt[e], Cc); s_cnt[e] = 0; }
        for (int s = 0; s < Ss; s++){
            int e = s_i2[s]; int p = s_cnt[e]++ + s_m1c[e];
            if (p < Cc){ s_p2[s] = p; s_slot[e*Cc+p] = s; } else s_p2[s] = -1;
        }
    }
    __syncthreads();
    for (int i = tid; i < Ee*Cc; i += blockDim.x){
        int e = i/Cc, c = i%Cc;
        g_slotsrc[e*GCv + g*Cc + c] = s_slot[i];
    }
    for (int s = tid; s < Ss; s += blockDim.x){
        int p1 = s_p1[s], p2 = s_p2[s], e1 = s_i1[s], e2 = s_i2[s];
        g_tokinfo[g*Ss+s] = make_int2(p1 >= 0 ? e1*GCv + g*Cc + p1 : -1,
                                      p2 >= 0 ? e2*GCv + g*Cc + p2 : -1);
    }
}

// ---------- splitT body ----------
__device__ __forceinline__ void splitT_body(const float* __restrict__ src,
                                            __nv_bfloat16* __restrict__ dhi,
                                            __nv_bfloat16* __restrict__ dlo,
                                            int e, int r0, int c0,
                                            int R, int C, int Cp, int Rp, int tid){
    __shared__ float t[32][33];
    int tx = tid & 31, ty = tid >> 5;
    const float* s = src + (size_t)e*R*C;
#pragma unroll
    for (int i = 0; i < 4; i++){
        int rr = r0+ty+i*8, cc = c0+tx;
        t[ty+i*8][tx] = (rr < R && cc < C) ? s[(size_t)rr*C+cc] : 0.f;
    }
    __syncthreads();
    size_t dbase = (size_t)e*Cp*Rp;
#pragma unroll
    for (int i = 0; i < 4; i++){
        int dr = c0+ty+i*8, dc = r0+tx;
        __nv_bfloat16 h,l; split1(t[tx][ty+i*8], h, l);
        dhi[dbase + (size_t)dr*Rp + dc] = h;
        dlo[dbase + (size_t)dr*Rp + dc] = l;
    }
}

// ---------- fused prep ----------
#define NGATH (Ee*GCv)
#define NSPL  ((Mdim/32)*(Hp/32)*Ee)
__global__ void k_prep(const float* __restrict__ x,
                       const float* __restrict__ w0,
                       const float* __restrict__ w1){
    int b = blockIdx.x;
    int tid = threadIdx.x;
    if (b < NGATH){
        int row = b;
        int g = (row % GCv) / Cc;
        int src = g_slotsrc[row];
        float4 v = make_float4(0.f,0.f,0.f,0.f);
        if (src >= 0) v = ((const float4*)(x + (size_t)(g*Ss+src)*Mdim))[tid];
        __nv_bfloat16 h0,l0,h1,l1,h2,l2,h3,l3;
        split1(v.x,h0,l0); split1(v.y,h1,l1); split1(v.z,h2,l2); split1(v.w,h3,l3);
        ((uint2*)(g_a_hi + (size_t)row*Mdim))[tid] = make_uint2(packbf(h0,h1), packbf(h2,h3));
        ((uint2*)(g_a_lo + (size_t)row*Mdim))[tid] = make_uint2(packbf(l0,l1), packbf(l2,l3));
    } else {
        int b2 = b - NGATH;
        int which = b2 / NSPL;
        int r = b2 % NSPL;
        int bx = r % (Mdim/32);
        int by = (r / (Mdim/32)) % (Hp/32);
        int e  = r / ((Mdim/32)*(Hp/32));
        const float* src = which ? w1 : w0;
        __nv_bfloat16* dhi = which ? g_w1t_hi : g_w0t_hi;
        __nv_bfloat16* dlo = which ? g_w1t_lo : g_w0t_lo;
        splitT_body(src, dhi, dlo, e, bx*32, by*32, Mdim, Hh, Hp, Mdim, tid);
    }
}

// ---------- splitT for wo ----------
__global__ void k_splitT_wo(const float* __restrict__ wo){
    int bx = blockIdx.x, by = blockIdx.y, e = blockIdx.z;
    splitT_body(wo, g_wot_hi, g_wot_lo, e, bx*32, by*32, Hh, Mdim, Mdim, Hp, threadIdx.x);
}

#define ROWB    80
#define MATB_A  10240       // 128 rows x 80B
#define MATB_B  5120        // 64 rows x 80B
#define MATB    10240       // for gemm2 (all 128-row tiles)

// ---------- GEMM1: warp-split W0/W1 (no spills) ----------
// CTA tile: M=128, N=64. Warps 0-3 compute A@W0 (64x32 each, 2x2), warps 4-7 A@W1.
// Epilogue: W0 warps stage d0 via smem; W1 warps do gelu(d0)*d1 -> hid hi/lo.
#define STG1 (2*MATB_A + 4*MATB_B)   // 40960
__global__ void __launch_bounds__(256, 1) k_mma1(){
    constexpr int K = Mdim;
    constexpr int NKS = K / 32;

    extern __shared__ __align__(128) char smem[];
    const uint32_t sb = s2u(smem);

    const int tid  = threadIdx.x;
    const int lane = tid & 31;
    const int wrp  = tid >> 5;
    const int wg   = wrp >> 2;             // 0 = W0, 1 = W1
    const int wm   = (wrp & 1) * 64;
    const int wn   = ((wrp >> 1) & 1) * 32;
    const int e  = blockIdx.z;
    const int bm = blockIdx.y * 128;
    const int bn = blockIdx.x * 64;

    const char* pA0 = (const char*)(g_a_hi   + ((size_t)e*GCv + bm)*K);
    const char* pA1 = (const char*)(g_a_lo   + ((size_t)e*GCv + bm)*K);
    const char* pB0 = (const char*)(g_w0t_hi + ((size_t)e*Hp  + bn)*K);
    const char* pB1 = (const char*)(g_w0t_lo + ((size_t)e*Hp  + bn)*K);
    const char* pB2 = (const char*)(g_w1t_hi + ((size_t)e*Hp  + bn)*K);
    const char* pB3 = (const char*)(g_w1t_lo + ((size_t)e*Hp  + bn)*K);

    // A loads: 2 chunks/thread/mat; B loads: 1 chunk/thread/mat
    const int ra0 = (tid*2)     >> 2, qa0 = ((tid*2)     & 3)*16;
    const int ra1 = (tid*2 + 1) >> 2, qa1 = ((tid*2 + 1) & 3)*16;
    const int rbx = tid >> 2,         qbx = (tid & 3)*16;

    auto load_stage = [&](int ks, int buf){
        uint32_t s = sb + buf*STG1;
        size_t ko = (size_t)ks * 64;
        cpa16(s + ra0*ROWB + qa0, pA0 + (size_t)ra0*(K*2) + ko + qa0);
        cpa16(s + ra1*ROWB + qa1, pA1 + (size_t)ra1*(K*2) + ko + qa1);  // note: interleave below fixes both
        cpa16(s + MATB_A + ra0*ROWB + qa0, pA1 + (size_t)ra0*(K*2) + ko + qa0);
        cpa16(s + (tid*2+1 < 512 ? 0 : 0) + ra1*ROWB + qa1, pA0 + (size_t)ra1*(K*2) + ko + qa1);
        uint32_t sB = s + 2*MATB_A;
        cpa16(sB + 0*MATB_B + rbx*ROWB + qbx, pB0 + (size_t)rbx*(K*2) + ko + qbx);
        cpa16(sB + 1*MATB_B + rbx*ROWB + qbx, pB1 + (size_t)rbx*(K*2) + ko + qbx);
        cpa16(sB + 2*MATB_B + rbx*ROWB + qbx, pB2 + (size_t)rbx*(K*2) + ko + qbx);
        cpa16(sB + 3*MATB_B + rbx*ROWB + qbx, pB3 + (size_t)rbx*(K*2) + ko + qbx);
        CP_COMMIT();
    };
    // fix A mapping cleanly: redo lambda (the above had a copy/paste hazard) — use explicit loop
    auto load_stage2 = [&](int ks, int buf){
        uint32_t s = sb + buf*STG1;
        size_t ko = (size_t)ks * 64;
#pragma unroll
        for (int it = 0; it < 2; it++){
            int ci = tid*2 + it;
            int r = ci >> 2, q = (ci & 3)*16;
            cpa16(s + r*ROWB + q,          pA0 + (size_t)r*(K*2) + ko + q);
            cpa16(s + MATB_A + r*ROWB + q, pA1 + (size_t)r*(K*2) + ko + q);
        }
        uint32_t sB = s + 2*MATB_A;
        cpa16(sB + 0*MATB_B + rbx*ROWB + qbx, pB0 + (size_t)rbx*(K*2) + ko + qbx);
        cpa16(sB + 1*MATB_B + rbx*ROWB + qbx, pB1 + (size_t)rbx*(K*2) + ko + qbx);
        cpa16(sB + 2*MATB_B + rbx*ROWB + qbx, pB2 + (size_t)rbx*(K*2) + ko + qbx);
        cpa16(sB + 3*MATB_B + rbx*ROWB + qbx, pB3 + (size_t)rbx*(K*2) + ko + qbx);
        CP_COMMIT();
    };
    (void)load_stage;

    float d[4][4][4];
#pragma unroll
    for (int i = 0; i < 4; i++)
#pragma unroll
        for (int j = 0; j < 4; j++)
#pragma unroll
            for (int q = 0; q < 4; q++) d[i][j][q] = 0.f;

    load_stage2(0, 0);
    load_stage2(1, 1);
    load_stage2(2, 2);

    const uint32_t bofs = 2*MATB_A + wg*(2*MATB_B);

    for (int ks = 0; ks < NKS; ks++){
        int buf = ks - (ks/3)*3;
        if (ks < NKS-2)       CP_WAIT2();
        else if (ks == NKS-2) CP_WAIT1();
        else                  CP_WAIT0();
        __syncthreads();
        uint32_t s0 = sb + buf*STG1;
#pragma unroll
        for (int kk = 0; kk < 2; kk++){
            uint32_t ah[4][4], al[4][4], bh[4][2], bl[4][2];
#pragma unroll
            for (int mt = 0; mt < 4; mt++){
                uint32_t ad = s0 + (uint32_t)(wm + mt*16 + (lane & 15))*ROWB
                                 + (uint32_t)(kk*16 + (lane >> 4)*8)*2;
                LDSM4(ah[mt], ad);
                LDSM4(al[mt], ad + MATB_A);
            }
#pragma unroll
            for (int nt = 0; nt < 4; nt++){
                uint32_t bd = s0 + bofs + (uint32_t)(wn + nt*8 + (lane & 7))*ROWB
                                 + (uint32_t)(kk*16 + ((lane >> 3) & 1)*8)*2;
                LDSM2(bh[nt], bd);
                LDSM2(bl[nt], bd + MATB_B);
            }
#pragma unroll
            for (int mt = 0; mt < 4; mt++)
#pragma unroll
                for (int nt = 0; nt < 4; nt++){
                    MMA_BF16(d[mt][nt], ah[mt], bh[nt]);
                    MMA_BF16(d[mt][nt], ah[mt], bl[nt]);
                    MMA_BF16(d[mt][nt], al[mt], bh[nt]);
                }
        }
        __syncthreads();
        if (ks + 3 < NKS) load_stage2(ks + 3, buf);
    }

    // epilogue: W0 warps stage d0 through smem; W1 warps combine
    float* fb = (float*)smem;          // 64 x 128 floats = 32KB, layout fb[i*128 + t]
    __syncthreads();
    if (wg == 0){
#pragma unroll
        for (int mt = 0; mt < 4; mt++)
#pragma unroll
            for (int nt = 0; nt < 4; nt++)
#pragma unroll
                for (int q = 0; q < 4; q++)
                    fb[(mt*16 + nt*4 + q)*128 + tid] = d[mt][nt][q];
    }
    __syncthreads();
    if (wg == 1){
        int t = tid - 128;
        const int rb = bm + wm + (lane >> 2);
        const int cb = bn + wn + 2*(lane & 3);
#pragma unroll
        for (int mt = 0; mt < 4; mt++)
#pragma unroll
            for (int nt = 0; nt < 4; nt++)
#pragma unroll
                for (int h = 0; h < 2; h++){
                    int row = rb + mt*16 + h*8;
                    int col = cb + nt*8;
                    float v0a = fb[(mt*16 + nt*4 + h*2 + 0)*128 + t];
                    float v0b = fb[(mt*16 + nt*4 + h*2 + 1)*128 + t];
                    float v1a = d[mt][nt][h*2+0];
                    float v1b = d[mt][nt][h*2+1];
                    float ha = gelu_f(v0a)*v1a, hb = gelu_f(v0b)*v1b;
                    __nv_bfloat16 ahh, alo, bhh, blo;
                    split1(ha, ahh, alo); split1(hb, bhh, blo);
                    size_t idx = ((size_t)e*GCv + row)*(size_t)Hp + col;
                    *(uint32_t*)(g_hid_hi + idx) = packbf(ahh, bhh);
                    *(uint32_t*)(g_hid_lo + idx) = packbf(alo, blo);
                }
    }
}

// ---------- GEMM2: hid(hi/lo) x woT(hi/lo) -> expout fp32 ----------
#define STG2 (4*MATB)
__global__ void __launch_bounds__(256, 1) k_mma2(){
    constexpr int K = Hp;
    constexpr int N = Mdim;
    constexpr int NKS = K / 32;

    extern __shared__ __align__(128) char smem[];
    const uint32_t sb = s2u(smem);

    const int tid  = threadIdx.x;
    const int lane = tid & 31;
    const int wrp  = tid >> 5;
    const int wm   = (wrp >> 2) * 64;
    const int wn   = (wrp & 3) * 32;
    const int e  = blockIdx.z;
    const int bm = blockIdx.y * 128;
    const int bn = blockIdx.x * 128;

    const char* p[4];
    p[0] = (const char*)(g_hid_hi + ((size_t)e*GCv + bm)*K);
    p[1] = (const char*)(g_hid_lo + ((size_t)e*GCv + bm)*K);
    p[2] = (const char*)(g_wot_hi + ((size_t)e*N   + bn)*K);
    p[3] = (const char*)(g_wot_lo + ((size_t)e*N   + bn)*K);

    const int ci0 = tid*2, ci1 = tid*2 + 1;
    const int r0c = ci0 >> 2, q0 = (ci0 & 3)*16;
    const int r1c = ci1 >> 2, q1 = (ci1 & 3)*16;

    auto load_stage = [&](int ks, int buf){
        uint32_t s = sb + buf*STG2;
        size_t ko = (size_t)ks * 64;
#pragma unroll
        for (int m = 0; m < 4; m++){
            uint32_t d = s + m*MATB;
            cpa16(d + r0c*ROWB + q0, p[m] + (size_t)r0c*(K*2) + ko + q0);
            cpa16(d + r1c*ROWB + q1, p[m] + (size_t)r1c*(K*2) + ko + q1);
        }
        CP_COMMIT();
    };

    float d[4][4][4];
#pragma unroll
    for (int i = 0; i < 4; i++)
#pragma unroll
        for (int j = 0; j < 4; j++)
#pragma unroll
            for (int q = 0; q < 4; q++) d[i][j][q] = 0.f;

    load_stage(0, 0);
    load_stage(1, 1);
    load_stage(2, 2);

    for (int ks = 0; ks < NKS; ks++){
        int buf = ks - (ks/3)*3;
        if (ks < NKS-2)       CP_WAIT2();
        else if (ks == NKS-2) CP_WAIT1();
        else                  CP_WAIT0();
        __syncthreads();
        uint32_t s0 = sb + buf*STG2;
#pragma unroll
        for (int kk = 0; kk < 2; kk++){
            uint32_t ah[4][4], al[4][4], bh[4][2], bl[4][2];
#pragma unroll
            for (int mt = 0; mt < 4; mt++){
                uint32_t ad = s0 + (uint32_t)(wm + mt*16 + (lane & 15))*ROWB
                                 + (uint32_t)(kk*16 + (lane >> 4)*8)*2;
                LDSM4(ah[mt], ad);
                LDSM4(al[mt], ad + MATB);
            }
#pragma unroll
            for (int nt = 0; nt < 4; nt++){
                uint32_t bd = s0 + 2*MATB + (uint32_t)(wn + nt*8 + (lane & 7))*ROWB
                                 + (uint32_t)(kk*16 + ((lane >> 3) & 1)*8)*2;
                LDSM2(bh[nt], bd);
                LDSM2(bl[nt], bd + MATB);
            }
#pragma unroll
            for (int mt = 0; mt < 4; mt++)
#pragma unroll
                for (int nt = 0; nt < 4; nt++){
                    MMA_BF16(d[mt][nt], ah[mt], bh[nt]);
                    MMA_BF16(d[mt][nt], ah[mt], bl[nt]);
                    MMA_BF16(d[mt][nt], al[mt], bh[nt]);
                }
        }
        __syncthreads();
        if (ks + 3 < NKS) load_stage(ks + 3, buf);
    }

    const int rb = bm + wm + (lane >> 2);
    const int cb = bn + wn + 2*(lane & 3);
#pragma unroll
    for (int mt = 0; mt < 4; mt++)
#pragma unroll
        for (int nt = 0; nt < 4; nt++)
#pragma unroll
            for (int h = 0; h < 2; h++){
                int row = rb + mt*16 + h*8;
                int col = cb + nt*8;
                size_t idx = ((size_t)e*GCv + row)*(size_t)Mdim + col;
                *(float2*)(g_expout + idx) = make_float2(d[mt][nt][h*2+0], d[mt][nt][h*2+1]);
            }
}

// ---------- combine ----------
__global__ void k_combine(float* __restrict__ out){
    int t = blockIdx.x, i = threadIdx.x;
    int2 info = g_tokinfo[t];
    float4 acc = make_float4(0.f,0.f,0.f,0.f);
    if (info.x >= 0){
        float gv = g_gate1[t];
        float4 v = ((const float4*)(g_expout + (size_t)info.x*Mdim))[i];
        acc.x += gv*v.x; acc.y += gv*v.y; acc.z += gv*v.z; acc.w += gv*v.w;
    }
    if (info.y >= 0){
        float gv = g_gate2[t];
        float4 v = ((const float4*)(g_expout + (size_t)info.y*Mdim))[i];
        acc.x += gv*v.x; acc.y += gv*v.y; acc.z += gv*v.z; acc.w += gv*v.w;
    }
    ((float4*)(out + (size_t)t*Mdim))[i] = acc;
}

// ---------- launch ----------
extern "C" void kernel_launch(void* const* d_in, const int* in_sizes, int n_in,
                              void* d_out, int out_size){
    const float* x  = (const float*)d_in[0];
    const float* rw = (const float*)d_in[1];
    const float* w0 = (const float*)d_in[2];
    const float* w1 = (const float*)d_in[3];
    const float* wo = (const float*)d_in[4];
    float* out = (float*)d_out;

    static bool attr_done = false;
    if (!attr_done){
        cudaFuncSetAttribute(k_mma1, cudaFuncAttributeMaxDynamicSharedMemorySize, 3*STG1);
        cudaFuncSetAttribute(k_mma2, cudaFuncAttributeMaxDynamicSharedMemorySize, 3*STG2);
        attr_done = true;
    }

    // k_mma1 is the 4th launch (the one ncu captures)
    k_router<<<Ntok/8, 256>>>(x, rw);                                   // 1
    k_capacity<<<Gg, 256>>>();                                          // 2
    k_prep<<<NGATH + 2*NSPL, 256>>>(x, w0, w1);                         // 3
    k_mma1<<<dim3(Hp/64, GCv/128, Ee), 256, 3*STG1>>>();                // 4 <- profiled
    k_splitT_wo<<<dim3(Hh/32 + 1, Mdim/32, Ee), 256>>>(wo);             // 5
    k_mma2<<<dim3(Mdim/128, GCv/128, Ee), 256, 3*STG2>>>();             // 6
    k_combine<<<Ntok, 256>>>(out);                                      // 7
}